// round 2
// baseline (speedup 1.0000x reference)
#include <cuda_runtime.h>
#include <math.h>

#define B  4096
#define T  28
#define H  128
#define F0 28
#define NL 10
#define NC 10
#define BT 32
#define NTHREADS 256

// Ping-pong activation buffers [B, T, H] (static device globals: no allocation)
__device__ float g_bufA[(size_t)B * T * H];
__device__ float g_bufB[(size_t)B * T * H];

typedef unsigned long long ull;

// Packed fp32x2 FMA (Blackwell FFMA2) — only reachable via PTX
__device__ __forceinline__ void fma2(ull &d, ull a, ull b) {
    asm("fma.rn.f32x2 %0, %1, %2, %0;" : "+l"(d) : "l"(a), "l"(b));
}
__device__ __forceinline__ float f2lo(ull v) { return __int_as_float((int)(unsigned)(v & 0xffffffffULL)); }
__device__ __forceinline__ float f2hi(ull v) { return __int_as_float((int)(unsigned)(v >> 32)); }

// Fused layer kernel: xp = x @ Wih^T ; h = tanh(xp + b + h @ Whh^T), 28 steps.
// Block = 256 threads handles BT=32 batch rows. Weights + h state in SMEM.
// Thread (btg = tid&15, jg = tid>>4) computes j = jg*8..jg*8+7 for bt = btg and btg+16.
template <int F>
__global__ void __launch_bounds__(NTHREADS, 1)
rnn_layer(const float* __restrict__ in,   // [B, T, F]
          const float* __restrict__ Wih,  // [H, F]
          const float* __restrict__ Whh,  // [H, H]
          const float* __restrict__ bih,  // [H]
          const float* __restrict__ bhh,  // [H]
          float* __restrict__ out)        // [B, T, H]
{
    constexpr int FP = F + 2;   // padded row stride (even -> f32x2 aligned)
    constexpr int HP = H + 2;   // 130: bank = (2*bt + 2k) % 32, conflict-free

    extern __shared__ float smem[];
    float* Wih_s  = smem;                  // H * FP
    float* Whh_s  = Wih_s + H * FP;        // H * HP
    float* h_s    = Whh_s + H * HP;        // BT * HP
    float* x_s    = h_s + BT * HP;         // BT * FP
    float* bias_s = x_s + BT * FP;         // H

    const int tid = threadIdx.x;
    const int b0  = blockIdx.x * BT;

    // Load weights (one-time per layer per CTA; broadcast-reused 28*32 times)
    for (int i = tid; i < H * F; i += NTHREADS) {
        int j = i / F, k = i - j * F;
        Wih_s[j * FP + k] = Wih[i];
    }
    for (int i = tid; i < H * H; i += NTHREADS) {
        int j = i >> 7, k = i & 127;
        Whh_s[j * HP + k] = Whh[i];
    }
    if (tid < H) bias_s[tid] = bih[tid] + bhh[tid];
    for (int i = tid; i < BT * HP; i += NTHREADS) h_s[i] = 0.0f;
    __syncthreads();

    const int btg = tid & 15;
    const int jg  = tid >> 4;
    const int j0  = jg * 8;

    const ull* xr0  = reinterpret_cast<const ull*>(x_s + btg * FP);
    const ull* xr1  = reinterpret_cast<const ull*>(x_s + (btg + 16) * FP);
    const ull* hr0  = reinterpret_cast<const ull*>(h_s + btg * HP);
    const ull* hr1  = reinterpret_cast<const ull*>(h_s + (btg + 16) * HP);
    const ull* Wih2 = reinterpret_cast<const ull*>(Wih_s);
    const ull* Whh2 = reinterpret_cast<const ull*>(Whh_s);

    for (int t = 0; t < T; ++t) {
        // Stage x_t for the 32 batch rows (coalesced)
        for (int i = tid; i < BT * F; i += NTHREADS) {
            int bt = i / F, f = i - bt * F;
            x_s[bt * FP + f] = in[((size_t)(b0 + bt) * T + t) * F + f];
        }
        __syncthreads();

        ull a0[8], a1[8];
#pragma unroll
        for (int jj = 0; jj < 8; jj++) { a0[jj] = 0ULL; a1[jj] = 0ULL; }

        // Input projection dot (F terms)
#pragma unroll 4
        for (int kk = 0; kk < F / 2; ++kk) {
            ull x0 = xr0[kk], x1 = xr1[kk];
#pragma unroll
            for (int jj = 0; jj < 8; jj++) {
                ull w = Wih2[(j0 + jj) * (FP / 2) + kk];
                fma2(a0[jj], x0, w);
                fma2(a1[jj], x1, w);
            }
        }
        // Recurrent dot (H terms)
#pragma unroll 4
        for (int kk = 0; kk < H / 2; ++kk) {
            ull h0 = hr0[kk], h1 = hr1[kk];
#pragma unroll
            for (int jj = 0; jj < 8; jj++) {
                ull w = Whh2[(j0 + jj) * (HP / 2) + kk];
                fma2(a0[jj], h0, w);
                fma2(a1[jj], h1, w);
            }
        }

        float v0[8], v1[8];
#pragma unroll
        for (int jj = 0; jj < 8; jj++) {
            float bsum = bias_s[j0 + jj];
            v0[jj] = tanhf(f2lo(a0[jj]) + f2hi(a0[jj]) + bsum);
            v1[jj] = tanhf(f2lo(a1[jj]) + f2hi(a1[jj]) + bsum);
        }

        __syncthreads();  // all reads of old h_s complete before overwrite

#pragma unroll
        for (int jj = 0; jj < 8; jj++) {
            h_s[btg * HP + j0 + jj]        = v0[jj];
            h_s[(btg + 16) * HP + j0 + jj] = v1[jj];
        }
        // Global store of this timestep's hidden state (2x float4 per bt)
        float* o0 = out + ((size_t)(b0 + btg) * T + t) * H + j0;
        float* o1 = out + ((size_t)(b0 + btg + 16) * T + t) * H + j0;
        reinterpret_cast<float4*>(o0)[0] = make_float4(v0[0], v0[1], v0[2], v0[3]);
        reinterpret_cast<float4*>(o0)[1] = make_float4(v0[4], v0[5], v0[6], v0[7]);
        reinterpret_cast<float4*>(o1)[0] = make_float4(v1[0], v1[1], v1[2], v1[3]);
        reinterpret_cast<float4*>(o1)[1] = make_float4(v1[4], v1[5], v1[6], v1[7]);
        __syncthreads();  // h_s fully written before next step's reads
    }
}

// Final FC on last timestep: out[b, c] = h[b, T-1, :] . fc_W[c, :] + fc_b[c]
__global__ void fc_kernel(const float* __restrict__ act, const float* __restrict__ fcW,
                          const float* __restrict__ fcb, float* __restrict__ out)
{
    int i = blockIdx.x * blockDim.x + threadIdx.x;
    if (i >= B * NC) return;
    int b = i / NC, c = i - b * NC;
    const float* h = act + ((size_t)b * T + (T - 1)) * H;
    const float* w = fcW + c * H;
    float acc = fcb[c];
#pragma unroll 8
    for (int k = 0; k < H; ++k) acc += h[k] * w[k];
    out[i] = acc;
}

extern "C" void kernel_launch(void* const* d_in, const int* in_sizes, int n_in,
                              void* d_out, int out_size)
{
    const float* x    = (const float*)d_in[0];
    const float* Wih0 = (const float*)d_in[1];
    const float* Wih  = (const float*)d_in[2];  // [NL-1, H, H]
    const float* Whh  = (const float*)d_in[3];  // [NL, H, H]
    const float* bih  = (const float*)d_in[4];  // [NL, H]
    const float* bhh  = (const float*)d_in[5];  // [NL, H]
    const float* fcW  = (const float*)d_in[6];
    const float* fcb  = (const float*)d_in[7];
    float* out = (float*)d_out;

    float *bufA, *bufB;
    cudaGetSymbolAddress((void**)&bufA, g_bufA);
    cudaGetSymbolAddress((void**)&bufB, g_bufB);

    const int smem128 = (H * 130 + H * 130 + BT * 130 + BT * 130 + H) * (int)sizeof(float);
    const int smem28  = (H * 30 + H * 130 + BT * 130 + BT * 30 + H) * (int)sizeof(float);

    static bool attr_set = false;
    if (!attr_set) {
        cudaFuncSetAttribute(rnn_layer<F0>, cudaFuncAttributeMaxDynamicSharedMemorySize, smem28);
        cudaFuncSetAttribute(rnn_layer<H>,  cudaFuncAttributeMaxDynamicSharedMemorySize, smem128);
        attr_set = true;
    }

    // Layer 0 (F = 28)
    rnn_layer<F0><<<B / BT, NTHREADS, smem28>>>(x, Wih0, Whh, bih, bhh, bufA);

    // Layers 1..9 (F = 128), ping-pong buffers
    const float* cur = bufA;
    float* nxt = bufB;
    for (int l = 1; l < NL; ++l) {
        rnn_layer<H><<<B / BT, NTHREADS, smem128>>>(
            cur,
            Wih + (size_t)(l - 1) * H * H,
            Whh + (size_t)l * H * H,
            bih + (size_t)l * H,
            bhh + (size_t)l * H,
            nxt);
        const float* tmp = nxt;
        nxt = (float*)cur;
        cur = tmp;
    }

    fc_kernel<<<(B * NC + 255) / 256, 256>>>(cur, fcW, fcb, out);
}

// round 3
// speedup vs baseline: 1.2983x; 1.2983x over previous
#include <cuda_runtime.h>
#include <math.h>
#include <stdint.h>

#define B  4096
#define T  28
#define H  128
#define F0 28
#define NL 10
#define NC 10
#define BT 32          // batch rows per CTA
#define CTAS (B / BT)  // 128
#define NTHREADS 256

// Static device buffers (no allocation allowed)
__device__ float g_bufA[(size_t)B * T * H];   // activations ping
__device__ float g_bufB[(size_t)B * T * H];   // activations pong
__device__ float g_xp [(size_t)B * T * H];    // xp scratch in fragment order

// ---------------------------------------------------------------------------
// tf32 helpers
// ---------------------------------------------------------------------------
__device__ __forceinline__ uint32_t f2tf(float x) {
    uint32_t r; asm("cvt.rna.tf32.f32 %0, %1;" : "=r"(r) : "f"(x)); return r;
}
__device__ __forceinline__ void split_tf32(float x, uint32_t &hi, uint32_t &lo) {
    hi = f2tf(x);
    lo = f2tf(x - __uint_as_float(hi));
}
// D += A(16x8, tf32) * B(8x8, tf32), fp32 accumulate
__device__ __forceinline__ void mma8(float c[4], uint4 a, const uint32_t b[2]) {
    asm volatile("mma.sync.aligned.m16n8k8.row.col.f32.tf32.tf32.f32 "
        "{%0,%1,%2,%3}, {%4,%5,%6,%7}, {%8,%9}, {%0,%1,%2,%3};"
        : "+f"(c[0]), "+f"(c[1]), "+f"(c[2]), "+f"(c[3])
        : "r"(a.x), "r"(a.y), "r"(a.z), "r"(a.w), "r"(b[0]), "r"(b[1]));
}
// tanh via MUFU.EX2 + MUFU.RCP (abs err ~1e-6): tanh(x) = 1 - 2/(exp(2x)+1)
__device__ __forceinline__ float fast_tanh(float x) {
    float e; asm("ex2.approx.f32 %0, %1;" : "=f"(e) : "f"(x * 2.8853900817779268f));
    float r; asm("rcp.approx.f32 %0, %1;" : "=f"(r) : "f"(e + 1.0f));
    return fmaf(-2.0f, r, 1.0f);
}

// Fragment permutation index for A operand staging:
// element (r in 0..15, f in 0..K-1) -> A_s[kc*128 + lane*4 + reg]
__device__ __forceinline__ int perm_idx(int r, int f) {
    int kc = f >> 3, c = f & 7, g = r & 7;
    int reg = (r >> 3) | ((c & 4) >> 1);
    return kc * 128 + (((g << 2) + (c & 3)) << 2) + reg;
}

// ---------------------------------------------------------------------------
// Fused per-layer kernel: phase1 xp GEMM + phase2 recurrent scan (tf32 MMA)
//   FIN: input feature count (28 or 128); KCIN = ceil(FIN/8)
// ---------------------------------------------------------------------------
template <int FIN, int KCIN>
__global__ void __launch_bounds__(NTHREADS, 1)
rnn_layer_mma(const float* __restrict__ in,   // [B, T, FIN]
              const float* __restrict__ Wih,  // [H, FIN]
              const float* __restrict__ Whh,  // [H, H]
              const float* __restrict__ bih,  // [H]
              const float* __restrict__ bhh,  // [H]
              float* __restrict__ out,        // [B, T, H]
              float* __restrict__ xps)        // frag-order scratch
{
    constexpr int KPAD = KCIN * 8;

    // SMEM: A-operand fragment store, hi/lo. Scan uses 2 m-tiles x 16 kc x 128.
    __shared__ __align__(16) uint32_t As_hi[2 * 16 * 128];
    __shared__ __align__(16) uint32_t As_lo[2 * 16 * 128];

    const int tid  = threadIdx.x;
    const int lane = tid & 31;
    const int w    = tid >> 5;          // warp id 0..7 -> n-slice [16w, 16w+16)
    const int b0   = blockIdx.x * BT;
    float* xp = xps + (size_t)blockIdx.x * (56 * 2048);

    // Register-resident B fragments (hi/lo): [kc][ntile][2]
    uint32_t Bhi[16][2][2], Blo[16][2][2];

    // ---- load Wih fragments ----
#pragma unroll
    for (int kc = 0; kc < KCIN; ++kc)
#pragma unroll
        for (int nt = 0; nt < 2; ++nt) {
            int n  = w * 16 + nt * 8 + (lane >> 2);
            int k0 = kc * 8 + (lane & 3);
            float v0 = (k0     < FIN) ? Wih[n * FIN + k0]     : 0.0f;
            float v1 = (k0 + 4 < FIN) ? Wih[n * FIN + k0 + 4] : 0.0f;
            split_tf32(v0, Bhi[kc][nt][0], Blo[kc][nt][0]);
            split_tf32(v1, Bhi[kc][nt][1], Blo[kc][nt][1]);
        }

    // bias values for this lane's C columns
    float binit[2][2];
#pragma unroll
    for (int nt = 0; nt < 2; ++nt) {
        int c0 = w * 16 + nt * 8 + (lane & 3) * 2;
        binit[nt][0] = bih[c0] + bhh[c0];
        binit[nt][1] = bih[c0 + 1] + bhh[c0 + 1];
    }

    // =======================================================================
    // PHASE 1: xp[mt] = x[mt] @ Wih^T + b   for 56 m16-tiles (rows = t*32+bt)
    // =======================================================================
    for (int mt = 0; mt < 56; ++mt) {
        const int t   = mt >> 1;
        const int btb = (mt & 1) * 16;
        // stage 16 rows of x into fragment-permuted SMEM (hi/lo split)
        for (int i = tid; i < 16 * KPAD; i += NTHREADS) {
            int r = i / KPAD, f = i - r * KPAD;
            float v = (f < FIN)
                ? in[((size_t)(b0 + btb + r) * T + t) * FIN + f] : 0.0f;
            uint32_t hi, lo; split_tf32(v, hi, lo);
            int idx = perm_idx(r, f);
            As_hi[idx] = hi; As_lo[idx] = lo;
        }
        __syncthreads();

        float acc[2][4];
#pragma unroll
        for (int nt = 0; nt < 2; ++nt) {
            acc[nt][0] = binit[nt][0]; acc[nt][1] = binit[nt][1];
            acc[nt][2] = binit[nt][0]; acc[nt][3] = binit[nt][1];
        }
#pragma unroll
        for (int kc = 0; kc < KCIN; ++kc) {
            uint4 ah = *(const uint4*)&As_hi[kc * 128 + lane * 4];
            uint4 al = *(const uint4*)&As_lo[kc * 128 + lane * 4];
#pragma unroll
            for (int nt = 0; nt < 2; ++nt) {
                mma8(acc[nt], ah, Bhi[kc][nt]);   // hi*hi
                mma8(acc[nt], al, Bhi[kc][nt]);   // lo*hi
                mma8(acc[nt], ah, Blo[kc][nt]);   // hi*lo
            }
        }
        // store accumulators in fragment order (coalesced)
        float4* dst = (float4*)(xp + (size_t)mt * 2048 + w * 256 + lane * 8);
        dst[0] = make_float4(acc[0][0], acc[0][1], acc[0][2], acc[0][3]);
        dst[1] = make_float4(acc[1][0], acc[1][1], acc[1][2], acc[1][3]);
        __syncthreads();
    }

    // =======================================================================
    // PHASE 2: scan  h = tanh(xp_t + h @ Whh^T)
    // =======================================================================
    // reload B fragments with Whh
#pragma unroll
    for (int kc = 0; kc < 16; ++kc)
#pragma unroll
        for (int nt = 0; nt < 2; ++nt) {
            int n  = w * 16 + nt * 8 + (lane >> 2);
            int k0 = kc * 8 + (lane & 3);
            split_tf32(Whh[n * H + k0],     Bhi[kc][nt][0], Blo[kc][nt][0]);
            split_tf32(Whh[n * H + k0 + 4], Bhi[kc][nt][1], Blo[kc][nt][1]);
        }
    // h = 0
    for (int i = tid; i < 2 * 16 * 128; i += NTHREADS) { As_hi[i] = 0u; As_lo[i] = 0u; }
    __syncthreads();

    for (int t = 0; t < T; ++t) {
        float acc[2][2][4];   // [mtile][ntile][4]
#pragma unroll
        for (int m2 = 0; m2 < 2; ++m2) {
            const float4* src =
                (const float4*)(xp + (size_t)(2 * t + m2) * 2048 + w * 256 + lane * 8);
            float4 v0 = src[0], v1 = src[1];
            acc[m2][0][0] = v0.x; acc[m2][0][1] = v0.y;
            acc[m2][0][2] = v0.z; acc[m2][0][3] = v0.w;
            acc[m2][1][0] = v1.x; acc[m2][1][1] = v1.y;
            acc[m2][1][2] = v1.z; acc[m2][1][3] = v1.w;
        }
#pragma unroll
        for (int kc = 0; kc < 16; ++kc) {
            uint4 a0h = *(const uint4*)&As_hi[kc * 128 + lane * 4];
            uint4 a0l = *(const uint4*)&As_lo[kc * 128 + lane * 4];
            uint4 a1h = *(const uint4*)&As_hi[2048 + kc * 128 + lane * 4];
            uint4 a1l = *(const uint4*)&As_lo[2048 + kc * 128 + lane * 4];
#pragma unroll
            for (int nt = 0; nt < 2; ++nt) {
                mma8(acc[0][nt], a0h, Bhi[kc][nt]);
                mma8(acc[0][nt], a0l, Bhi[kc][nt]);
                mma8(acc[0][nt], a0h, Blo[kc][nt]);
                mma8(acc[1][nt], a1h, Bhi[kc][nt]);
                mma8(acc[1][nt], a1l, Bhi[kc][nt]);
                mma8(acc[1][nt], a1h, Blo[kc][nt]);
            }
        }
        __syncthreads();   // all reads of old h complete

        // epilogue: tanh, write h back (perm SMEM) + activations (global)
#pragma unroll
        for (int m2 = 0; m2 < 2; ++m2)
#pragma unroll
            for (int nt = 0; nt < 2; ++nt)
#pragma unroll
                for (int half = 0; half < 2; ++half) {
                    float y0 = fast_tanh(acc[m2][nt][2 * half]);
                    float y1 = fast_tanh(acc[m2][nt][2 * half + 1]);
                    int rl  = (lane >> 2) + half * 8;       // row in m-tile
                    int bt  = m2 * 16 + rl;
                    int col = w * 16 + nt * 8 + (lane & 3) * 2;
                    *(float2*)&out[((size_t)(b0 + bt) * T + t) * H + col] =
                        make_float2(y0, y1);
                    int i0 = m2 * 2048 + perm_idx(rl, col);
                    int i1 = m2 * 2048 + perm_idx(rl, col + 1);
                    uint32_t hi, lo;
                    split_tf32(y0, hi, lo); As_hi[i0] = hi; As_lo[i0] = lo;
                    split_tf32(y1, hi, lo); As_hi[i1] = hi; As_lo[i1] = lo;
                }
        __syncthreads();   // h fully written before next step
    }
}

// ---------------------------------------------------------------------------
// Final FC on last timestep
// ---------------------------------------------------------------------------
__global__ void fc_kernel(const float* __restrict__ act, const float* __restrict__ fcW,
                          const float* __restrict__ fcb, float* __restrict__ out)
{
    int i = blockIdx.x * blockDim.x + threadIdx.x;
    if (i >= B * NC) return;
    int b = i / NC, c = i - b * NC;
    const float* h = act + ((size_t)b * T + (T - 1)) * H;
    const float* wgt = fcW + c * H;
    float s = fcb[c];
#pragma unroll 8
    for (int k = 0; k < H; ++k) s += h[k] * wgt[k];
    out[i] = s;
}

extern "C" void kernel_launch(void* const* d_in, const int* in_sizes, int n_in,
                              void* d_out, int out_size)
{
    const float* x    = (const float*)d_in[0];
    const float* Wih0 = (const float*)d_in[1];
    const float* Wih  = (const float*)d_in[2];  // [NL-1, H, H]
    const float* Whh  = (const float*)d_in[3];  // [NL, H, H]
    const float* bih  = (const float*)d_in[4];  // [NL, H]
    const float* bhh  = (const float*)d_in[5];  // [NL, H]
    const float* fcW  = (const float*)d_in[6];
    const float* fcb  = (const float*)d_in[7];
    float* out = (float*)d_out;

    float *bufA, *bufB, *xps;
    cudaGetSymbolAddress((void**)&bufA, g_bufA);
    cudaGetSymbolAddress((void**)&bufB, g_bufB);
    cudaGetSymbolAddress((void**)&xps,  g_xp);

    // Layer 0 (FIN=28 -> 4 k-chunks)
    rnn_layer_mma<F0, 4><<<CTAS, NTHREADS>>>(x, Wih0, Whh, bih, bhh, bufA, xps);

    // Layers 1..9 (FIN=128 -> 16 k-chunks)
    const float* cur = bufA;
    float* nxt = bufB;
    for (int l = 1; l < NL; ++l) {
        rnn_layer_mma<H, 16><<<CTAS, NTHREADS>>>(
            cur,
            Wih + (size_t)(l - 1) * H * H,
            Whh + (size_t)l * H * H,
            bih + (size_t)l * H,
            bhh + (size_t)l * H,
            nxt, xps);
        const float* tmp = nxt;
        nxt = (float*)cur;
        cur = tmp;
    }

    fc_kernel<<<(B * NC + 255) / 256, 256>>>(cur, fcW, fcb, out);
}

// round 4
// speedup vs baseline: 2.3358x; 1.7991x over previous
#include <cuda_runtime.h>
#include <cuda_fp16.h>
#include <math.h>
#include <stdint.h>

#define B  4096
#define T  28
#define H  128
#define F0 28
#define NL 10
#define NC 10
#define BT 32          // batch rows per CTA
#define CTAS (B / BT)  // 128
#define NT 512         // 16 warps

// Static device buffers (no allocation allowed)
__device__ float g_bufA[(size_t)B * T * H];
__device__ float g_bufB[(size_t)B * T * H];
__device__ float g_xp [(size_t)B * T * H];   // fragment-order xp scratch

// ---------------------------------------------------------------------------
// helpers
// ---------------------------------------------------------------------------
__device__ __forceinline__ uint32_t pack2(__half a, __half b) {
    __half2 h = __halves2half2(a, b);           // a -> low, b -> high
    return *reinterpret_cast<uint32_t*>(&h);
}
// split fp32 -> f16 hi + f16 lo (lo = round(x - hi))
__device__ __forceinline__ void split16(float x, __half &hi, __half &lo) {
    hi = __float2half_rn(x);
    lo = __float2half_rn(x - __half2float(hi));
}
// D += A(16x16 f16) * B(16x8 f16), fp32 accumulate
__device__ __forceinline__ void mma16(float c[4], uint4 a, const uint32_t b[2]) {
    asm volatile("mma.sync.aligned.m16n8k16.row.col.f32.f16.f16.f32 "
        "{%0,%1,%2,%3}, {%4,%5,%6,%7}, {%8,%9}, {%0,%1,%2,%3};"
        : "+f"(c[0]), "+f"(c[1]), "+f"(c[2]), "+f"(c[3])
        : "r"(a.x), "r"(a.y), "r"(a.z), "r"(a.w), "r"(b[0]), "r"(b[1]));
}
// tanh(x) = 1 - 2/(exp(2x)+1) via MUFU (abs err ~1e-6)
__device__ __forceinline__ float fast_tanh(float x) {
    float e; asm("ex2.approx.f32 %0, %1;" : "=f"(e) : "f"(x * 2.8853900817779268f));
    float r; asm("rcp.approx.f32 %0, %1;" : "=f"(r) : "f"(e + 1.0f));
    return fmaf(-2.0f, r, 1.0f);
}

// A-fragment word index for element (rl in 0..15, kk in 0..15) of one m16k16 tile
__device__ __forceinline__ int awidx(int rl, int kk) {
    int lane = ((rl & 7) << 2) | ((kk & 7) >> 1);
    int reg  = ((kk & 8) >> 2) | (rl >> 3);
    return lane * 4 + reg;               // half select = kk & 1
}

// ---------------------------------------------------------------------------
// Fused per-layer kernel (fp16 split-3 MMA)
//   FIN: input features (28 or 128), KC16 = ceil(FIN/16)
// Warp w: m2 = w>>3 (m-tile of 16 rows), ns = w&7 (n-cols [16ns,16ns+16))
// ---------------------------------------------------------------------------
template <int FIN, int KC16>
__global__ void __launch_bounds__(NT, 1)
rnn_layer_f16(const float* __restrict__ in,   // [B, T, FIN]
              const float* __restrict__ Wih,  // [H, FIN]
              const float* __restrict__ Whh,  // [H, H]
              const float* __restrict__ bih,
              const float* __restrict__ bhh,
              float* __restrict__ out,        // [B, T, H]
              float* __restrict__ xps,
              int last)
{
    constexpr int KPAD = KC16 * 16;

    // [buf][m2][kc][lane*4+reg] ; buf0 also used as phase-1 staging
    __shared__ __align__(16) uint32_t AsH[2 * 2048];
    __shared__ __align__(16) uint32_t AsL[2 * 2048];
    __half* AsHh = reinterpret_cast<__half*>(AsH);
    __half* AsLh = reinterpret_cast<__half*>(AsL);

    const int tid  = threadIdx.x;
    const int lane = tid & 31;
    const int w    = tid >> 5;
    const int m2   = w >> 3;
    const int ns   = w & 7;
    const int grp  = lane >> 2;
    const int tig  = lane & 3;
    const int b0   = blockIdx.x * BT;
    float* xp = xps + (size_t)blockIdx.x * (56 * 2048);

    uint32_t Bhi[8][2][2], Blo[8][2][2];

    // ---- Wih B-fragments ----
#pragma unroll
    for (int kc = 0; kc < KC16; ++kc)
#pragma unroll
        for (int nt = 0; nt < 2; ++nt) {
            int n  = ns * 16 + nt * 8 + grp;
            int k0 = kc * 16 + 2 * tig;
            float v00 = (k0     < FIN) ? Wih[n * FIN + k0]     : 0.0f;
            float v01 = (k0 + 1 < FIN) ? Wih[n * FIN + k0 + 1] : 0.0f;
            float v10 = (k0 + 8 < FIN) ? Wih[n * FIN + k0 + 8] : 0.0f;
            float v11 = (k0 + 9 < FIN) ? Wih[n * FIN + k0 + 9] : 0.0f;
            __half h0, l0, h1, l1;
            split16(v00, h0, l0); split16(v01, h1, l1);
            Bhi[kc][nt][0] = pack2(h0, h1); Blo[kc][nt][0] = pack2(l0, l1);
            split16(v10, h0, l0); split16(v11, h1, l1);
            Bhi[kc][nt][1] = pack2(h0, h1); Blo[kc][nt][1] = pack2(l0, l1);
        }

    // bias for this lane's C columns
    float binit[2][2];
#pragma unroll
    for (int nt = 0; nt < 2; ++nt) {
        int c0 = ns * 16 + nt * 8 + 2 * tig;
        binit[nt][0] = bih[c0] + bhh[c0];
        binit[nt][1] = bih[c0 + 1] + bhh[c0 + 1];
    }

    // =======================================================================
    // PHASE 1: xp = x @ Wih^T + b  (56 m16 tiles; 2 per t, one per m2 group)
    // =======================================================================
    for (int t = 0; t < T; ++t) {
        for (int i = tid; i < 32 * KPAD; i += NT) {
            int r = i / KPAD, k = i - r * KPAD;
            float v = (k < FIN)
                ? in[((size_t)(b0 + r) * T + t) * FIN + k] : 0.0f;
            __half hi, lo; split16(v, hi, lo);
            int word = (r >> 4) * 1024 + (k >> 4) * 128 + awidx(r & 15, k & 15);
            int hsel = k & 1;
            AsHh[2 * word + hsel] = hi;
            AsLh[2 * word + hsel] = lo;
        }
        __syncthreads();

        float acc[2][4];
#pragma unroll
        for (int nt = 0; nt < 2; ++nt) {
            acc[nt][0] = binit[nt][0]; acc[nt][1] = binit[nt][1];
            acc[nt][2] = binit[nt][0]; acc[nt][3] = binit[nt][1];
        }
#pragma unroll
        for (int kc = 0; kc < KC16; ++kc) {
            uint4 ah = *(const uint4*)&AsH[m2 * 1024 + kc * 128 + lane * 4];
            uint4 al = *(const uint4*)&AsL[m2 * 1024 + kc * 128 + lane * 4];
#pragma unroll
            for (int nt = 0; nt < 2; ++nt) {
                mma16(acc[nt], ah, Bhi[kc][nt]);
                mma16(acc[nt], al, Bhi[kc][nt]);
                mma16(acc[nt], ah, Blo[kc][nt]);
            }
        }
        float4* dst = (float4*)(xp + (size_t)(2 * t + m2) * 2048 + ns * 256 + lane * 8);
        dst[0] = make_float4(acc[0][0], acc[0][1], acc[0][2], acc[0][3]);
        dst[1] = make_float4(acc[1][0], acc[1][1], acc[1][2], acc[1][3]);
        __syncthreads();
    }

    // =======================================================================
    // PHASE 2: scan  h = tanh(xp_t + h @ Whh^T)
    // =======================================================================
#pragma unroll
    for (int kc = 0; kc < 8; ++kc)
#pragma unroll
        for (int nt = 0; nt < 2; ++nt) {
            int n  = ns * 16 + nt * 8 + grp;
            int k0 = kc * 16 + 2 * tig;
            __half h0, l0, h1, l1;
            split16(Whh[n * H + k0],     h0, l0);
            split16(Whh[n * H + k0 + 1], h1, l1);
            Bhi[kc][nt][0] = pack2(h0, h1); Blo[kc][nt][0] = pack2(l0, l1);
            split16(Whh[n * H + k0 + 8], h0, l0);
            split16(Whh[n * H + k0 + 9], h1, l1);
            Bhi[kc][nt][1] = pack2(h0, h1); Blo[kc][nt][1] = pack2(l0, l1);
        }
    for (int i = tid; i < 2 * 2048; i += NT) { AsH[i] = 0u; AsL[i] = 0u; }
    __syncthreads();

    const float4* xbase = (const float4*)(xp + (size_t)m2 * 2048 + ns * 256 + lane * 8);
    float4 xv0 = xbase[0], xv1 = xbase[1];   // prefetch t=0
    int p = 0;

    for (int t = 0; t < T; ++t) {
        float acc[2][4];
        acc[0][0] = xv0.x; acc[0][1] = xv0.y; acc[0][2] = xv0.z; acc[0][3] = xv0.w;
        acc[1][0] = xv1.x; acc[1][1] = xv1.y; acc[1][2] = xv1.z; acc[1][3] = xv1.w;
        if (t + 1 < T) {                     // prefetch next step's xp
            const float4* nx = xbase + (size_t)(t + 1) * 1024;  // 4096 floats/t
            xv0 = nx[0]; xv1 = nx[1];
        }
#pragma unroll
        for (int kc = 0; kc < 8; ++kc) {
            uint4 ah = *(const uint4*)&AsH[p * 2048 + m2 * 1024 + kc * 128 + lane * 4];
            uint4 al = *(const uint4*)&AsL[p * 2048 + m2 * 1024 + kc * 128 + lane * 4];
#pragma unroll
            for (int nt = 0; nt < 2; ++nt) {
                mma16(acc[nt], ah, Bhi[kc][nt]);
                mma16(acc[nt], al, Bhi[kc][nt]);
                mma16(acc[nt], ah, Blo[kc][nt]);
            }
        }

        // epilogue
        float y[2][4];
#pragma unroll
        for (int nt = 0; nt < 2; ++nt)
#pragma unroll
            for (int j = 0; j < 4; ++j) y[nt][j] = fast_tanh(acc[nt][j]);

        if (!last || t == T - 1) {
#pragma unroll
            for (int nt = 0; nt < 2; ++nt) {
                int c0 = ns * 16 + nt * 8 + 2 * tig;
                *(float2*)&out[((size_t)(b0 + m2 * 16 + grp)     * T + t) * H + c0] =
                    make_float2(y[nt][0], y[nt][1]);
                *(float2*)&out[((size_t)(b0 + m2 * 16 + grp + 8) * T + t) * H + c0] =
                    make_float2(y[nt][2], y[nt][3]);
            }
        }

        // write h (hi/lo f16) into the other buffer: one uint4 per array
        uint4 hv, lv;
        {
            __half h0, l0, h1, l1;
            split16(y[0][0], h0, l0); split16(y[0][1], h1, l1);
            hv.x = pack2(h0, h1); lv.x = pack2(l0, l1);
            split16(y[0][2], h0, l0); split16(y[0][3], h1, l1);
            hv.y = pack2(h0, h1); lv.y = pack2(l0, l1);
            split16(y[1][0], h0, l0); split16(y[1][1], h1, l1);
            hv.z = pack2(h0, h1); lv.z = pack2(l0, l1);
            split16(y[1][2], h0, l0); split16(y[1][3], h1, l1);
            hv.w = pack2(h0, h1); lv.w = pack2(l0, l1);
        }
        int wbase = (1 - p) * 2048 + m2 * 1024 + ns * 128 + lane * 4;
        *(uint4*)&AsH[wbase] = hv;
        *(uint4*)&AsL[wbase] = lv;

        __syncthreads();
        p ^= 1;
    }
}

// ---------------------------------------------------------------------------
// Final FC on last timestep
// ---------------------------------------------------------------------------
__global__ void fc_kernel(const float* __restrict__ act, const float* __restrict__ fcW,
                          const float* __restrict__ fcb, float* __restrict__ out)
{
    int i = blockIdx.x * blockDim.x + threadIdx.x;
    if (i >= B * NC) return;
    int b = i / NC, c = i - b * NC;
    const float* h = act + ((size_t)b * T + (T - 1)) * H;
    const float* wgt = fcW + c * H;
    float s = fcb[c];
#pragma unroll 8
    for (int k = 0; k < H; ++k) s += h[k] * wgt[k];
    out[i] = s;
}

extern "C" void kernel_launch(void* const* d_in, const int* in_sizes, int n_in,
                              void* d_out, int out_size)
{
    const float* x    = (const float*)d_in[0];
    const float* Wih0 = (const float*)d_in[1];
    const float* Wih  = (const float*)d_in[2];
    const float* Whh  = (const float*)d_in[3];
    const float* bih  = (const float*)d_in[4];
    const float* bhh  = (const float*)d_in[5];
    const float* fcW  = (const float*)d_in[6];
    const float* fcb  = (const float*)d_in[7];
    float* out = (float*)d_out;

    float *bufA, *bufB, *xps;
    cudaGetSymbolAddress((void**)&bufA, g_bufA);
    cudaGetSymbolAddress((void**)&bufB, g_bufB);
    cudaGetSymbolAddress((void**)&xps,  g_xp);

    rnn_layer_f16<F0, 2><<<CTAS, NT>>>(x, Wih0, Whh, bih, bhh, bufA, xps, 0);

    const float* cur = bufA;
    float* nxt = bufB;
    for (int l = 1; l < NL; ++l) {
        rnn_layer_f16<H, 8><<<CTAS, NT>>>(
            cur,
            Wih + (size_t)(l - 1) * H * H,
            Whh + (size_t)l * H * H,
            bih + (size_t)l * H,
            bhh + (size_t)l * H,
            nxt, xps, (l == NL - 1) ? 1 : 0);
        const float* tmp = nxt;
        nxt = (float*)cur;
        cur = tmp;
    }

    fc_kernel<<<(B * NC + 255) / 256, 256>>>(cur, fcW, fcb, out);
}

// round 5
// speedup vs baseline: 2.6499x; 1.1345x over previous
#include <cuda_runtime.h>
#include <cuda_fp16.h>
#include <math.h>
#include <stdint.h>

#define B  4096
#define T  28
#define H  128
#define F0 28
#define NL 10
#define NC 10
#define BT 16           // batch rows per CTA
#define CTAS (B / BT)   // 256
#define NT 256          // 8 warps

// Static device buffers (no allocation allowed).
// Packed activations: per CTA per t: 1024 hi words + 1024 lo words (f16x2),
// already in m16n8k16 A-fragment order.
__device__ uint32_t g_actA[(size_t)CTAS * T * 2048];
__device__ uint32_t g_actB[(size_t)CTAS * T * 2048];
__device__ float    g_xp  [(size_t)B * T * H];      // fp32 xp, fragment order
__device__ float    g_hlast[(size_t)B * H];         // last-timestep h (fp32)

// ---------------------------------------------------------------------------
// helpers
// ---------------------------------------------------------------------------
__device__ __forceinline__ uint32_t pack2(__half a, __half b) {
    __half2 h = __halves2half2(a, b);           // a -> low, b -> high
    return *reinterpret_cast<uint32_t*>(&h);
}
__device__ __forceinline__ void split16(float x, __half &hi, __half &lo) {
    hi = __float2half_rn(x);
    lo = __float2half_rn(x - __half2float(hi));
}
__device__ __forceinline__ void mma16(float c[4], uint4 a, const uint32_t b[2]) {
    asm volatile("mma.sync.aligned.m16n8k16.row.col.f32.f16.f16.f32 "
        "{%0,%1,%2,%3}, {%4,%5,%6,%7}, {%8,%9}, {%0,%1,%2,%3};"
        : "+f"(c[0]), "+f"(c[1]), "+f"(c[2]), "+f"(c[3])
        : "r"(a.x), "r"(a.y), "r"(a.z), "r"(a.w), "r"(b[0]), "r"(b[1]));
}
__device__ __forceinline__ float fast_tanh(float x) {
    float e; asm("ex2.approx.f32 %0, %1;" : "=f"(e) : "f"(x * 2.8853900817779268f));
    float r; asm("rcp.approx.f32 %0, %1;" : "=f"(r) : "f"(e + 1.0f));
    return fmaf(-2.0f, r, 1.0f);
}
// A-fragment word index for element (rl 0..15, kk 0..15) of one m16k16 tile
__device__ __forceinline__ int awidx(int rl, int kk) {
    int lane = ((rl & 7) << 2) | ((kk & 7) >> 1);
    int reg  = ((kk & 8) >> 2) | (rl >> 3);
    return lane * 4 + reg;               // half select = kk & 1
}

// ---------------------------------------------------------------------------
// Fused per-layer kernel. FIN=28: fp32 input via SMEM staging.
// FIN=128: packed-fragment input, direct global loads (no staging/barriers).
// Warp w = n-slice [16w, 16w+16); all 8 warps share the single m16 tile.
// ---------------------------------------------------------------------------
template <int FIN>
__global__ void __launch_bounds__(NT, 2)
rnn_layer(const float*    __restrict__ inf,   // fp32 input (FIN==28)
          const uint32_t* __restrict__ inp,   // packed input (FIN==128)
          const float*    __restrict__ Wih,   // [H, FIN]
          const float*    __restrict__ Whh,   // [H, H]
          const float*    __restrict__ bih,
          const float*    __restrict__ bhh,
          uint32_t*       __restrict__ outp,  // packed activations out
          float*          __restrict__ hlast, // [B, H] (last layer, t=T-1)
          float*          __restrict__ xps,
          int last)
{
    constexpr int KC16 = (FIN + 15) / 16;

    __shared__ __align__(16) uint32_t AsH[2048];   // [2 buf][1024]
    __shared__ __align__(16) uint32_t AsL[2048];

    const int tid  = threadIdx.x;
    const int lane = tid & 31;
    const int ns   = tid >> 5;          // warp id = n-slice
    const int grp  = lane >> 2;
    const int tig  = lane & 3;
    const int b0   = blockIdx.x * BT;
    float* xp = xps + (size_t)blockIdx.x * (T * 2048);
    const size_t actbase = (size_t)blockIdx.x * T * 2048;

    uint32_t Bhi[8][2][2], Blo[8][2][2];

    // ---- Wih B-fragments ----
#pragma unroll
    for (int kc = 0; kc < KC16; ++kc)
#pragma unroll
        for (int nt = 0; nt < 2; ++nt) {
            int n  = ns * 16 + nt * 8 + grp;
            int k0 = kc * 16 + 2 * tig;
            float v00 = (k0     < FIN) ? Wih[n * FIN + k0]     : 0.0f;
            float v01 = (k0 + 1 < FIN) ? Wih[n * FIN + k0 + 1] : 0.0f;
            float v10 = (k0 + 8 < FIN) ? Wih[n * FIN + k0 + 8] : 0.0f;
            float v11 = (k0 + 9 < FIN) ? Wih[n * FIN + k0 + 9] : 0.0f;
            __half h0, l0, h1, l1;
            split16(v00, h0, l0); split16(v01, h1, l1);
            Bhi[kc][nt][0] = pack2(h0, h1); Blo[kc][nt][0] = pack2(l0, l1);
            split16(v10, h0, l0); split16(v11, h1, l1);
            Bhi[kc][nt][1] = pack2(h0, h1); Blo[kc][nt][1] = pack2(l0, l1);
        }

    float binit[2][2];
#pragma unroll
    for (int nt = 0; nt < 2; ++nt) {
        int c0 = ns * 16 + nt * 8 + 2 * tig;
        binit[nt][0] = bih[c0] + bhh[c0];
        binit[nt][1] = bih[c0 + 1] + bhh[c0 + 1];
    }

    // =======================================================================
    // PHASE 1: xp = x @ Wih^T + b
    // =======================================================================
    if constexpr (FIN == 28) {
        __half* AsHh = reinterpret_cast<__half*>(AsH);
        __half* AsLh = reinterpret_cast<__half*>(AsL);
        for (int tp = 0; tp < T; tp += 2) {
            // stage two timesteps (one per buffer)
            for (int i = tid; i < 2 * 16 * 32; i += NT) {
                int tt = i >> 9, r = (i >> 5) & 15, k = i & 31;
                float v = (k < FIN)
                    ? inf[((size_t)(b0 + r) * T + (tp + tt)) * FIN + k] : 0.0f;
                __half hi, lo; split16(v, hi, lo);
                int word = tt * 1024 + (k >> 4) * 128 + awidx(r, k & 15);
                AsHh[2 * word + (k & 1)] = hi;
                AsLh[2 * word + (k & 1)] = lo;
            }
            __syncthreads();
#pragma unroll
            for (int tt = 0; tt < 2; ++tt) {
                float aH[2][4], aL1[2][4], aL2[2][4];
#pragma unroll
                for (int nt = 0; nt < 2; ++nt)
#pragma unroll
                    for (int j = 0; j < 4; ++j) {
                        aH[nt][j] = binit[nt][j & 1];
                        aL1[nt][j] = 0.0f; aL2[nt][j] = 0.0f;
                    }
#pragma unroll
                for (int kc = 0; kc < KC16; ++kc) {
                    uint4 ah = *(const uint4*)&AsH[tt * 1024 + kc * 128 + lane * 4];
                    uint4 al = *(const uint4*)&AsL[tt * 1024 + kc * 128 + lane * 4];
#pragma unroll
                    for (int nt = 0; nt < 2; ++nt) {
                        mma16(aH[nt],  ah, Bhi[kc][nt]);
                        mma16(aL1[nt], al, Bhi[kc][nt]);
                        mma16(aL2[nt], ah, Blo[kc][nt]);
                    }
                }
                float4* dst = (float4*)(xp + (size_t)(tp + tt) * 2048 + ns * 256 + lane * 8);
                dst[0] = make_float4(aH[0][0] + aL1[0][0] + aL2[0][0],
                                     aH[0][1] + aL1[0][1] + aL2[0][1],
                                     aH[0][2] + aL1[0][2] + aL2[0][2],
                                     aH[0][3] + aL1[0][3] + aL2[0][3]);
                dst[1] = make_float4(aH[1][0] + aL1[1][0] + aL2[1][0],
                                     aH[1][1] + aL1[1][1] + aL2[1][1],
                                     aH[1][2] + aL1[1][2] + aL2[1][2],
                                     aH[1][3] + aL1[1][3] + aL2[1][3]);
            }
            __syncthreads();
        }
    } else {
        // packed input already in fragment layout: direct loads, no barriers
        for (int t = 0; t < T; ++t) {
            const uint32_t* pb = inp + actbase + (size_t)t * 2048;
            float aH[2][4], aL1[2][4], aL2[2][4];
#pragma unroll
            for (int nt = 0; nt < 2; ++nt)
#pragma unroll
                for (int j = 0; j < 4; ++j) {
                    aH[nt][j] = binit[nt][j & 1];
                    aL1[nt][j] = 0.0f; aL2[nt][j] = 0.0f;
                }
#pragma unroll
            for (int kc = 0; kc < 8; ++kc) {
                uint4 ah = *(const uint4*)&pb[kc * 128 + lane * 4];
                uint4 al = *(const uint4*)&pb[1024 + kc * 128 + lane * 4];
#pragma unroll
                for (int nt = 0; nt < 2; ++nt) {
                    mma16(aH[nt],  ah, Bhi[kc][nt]);
                    mma16(aL1[nt], al, Bhi[kc][nt]);
                    mma16(aL2[nt], ah, Blo[kc][nt]);
                }
            }
            float4* dst = (float4*)(xp + (size_t)t * 2048 + ns * 256 + lane * 8);
            dst[0] = make_float4(aH[0][0] + aL1[0][0] + aL2[0][0],
                                 aH[0][1] + aL1[0][1] + aL2[0][1],
                                 aH[0][2] + aL1[0][2] + aL2[0][2],
                                 aH[0][3] + aL1[0][3] + aL2[0][3]);
            dst[1] = make_float4(aH[1][0] + aL1[1][0] + aL2[1][0],
                                 aH[1][1] + aL1[1][1] + aL2[1][1],
                                 aH[1][2] + aL1[1][2] + aL2[1][2],
                                 aH[1][3] + aL1[1][3] + aL2[1][3]);
        }
    }

    // =======================================================================
    // PHASE 2: scan  h = tanh(xp_t + h @ Whh^T)
    // =======================================================================
#pragma unroll
    for (int kc = 0; kc < 8; ++kc)
#pragma unroll
        for (int nt = 0; nt < 2; ++nt) {
            int n  = ns * 16 + nt * 8 + grp;
            int k0 = kc * 16 + 2 * tig;
            __half h0, l0, h1, l1;
            split16(Whh[n * H + k0],     h0, l0);
            split16(Whh[n * H + k0 + 1], h1, l1);
            Bhi[kc][nt][0] = pack2(h0, h1); Blo[kc][nt][0] = pack2(l0, l1);
            split16(Whh[n * H + k0 + 8], h0, l0);
            split16(Whh[n * H + k0 + 9], h1, l1);
            Bhi[kc][nt][1] = pack2(h0, h1); Blo[kc][nt][1] = pack2(l0, l1);
        }
    __syncthreads();
    for (int i = tid; i < 2048; i += NT) { AsH[i] = 0u; AsL[i] = 0u; }
    __syncthreads();

    const float4* src0 = (const float4*)(xp + ns * 256 + lane * 8);
    float4 xv0 = src0[0], xv1 = src0[1];     // prefetch t=0
    int p = 0;

    for (int t = 0; t < T; ++t) {
        float aH[2][4], aL1[2][4], aL2[2][4];
        aH[0][0] = xv0.x; aH[0][1] = xv0.y; aH[0][2] = xv0.z; aH[0][3] = xv0.w;
        aH[1][0] = xv1.x; aH[1][1] = xv1.y; aH[1][2] = xv1.z; aH[1][3] = xv1.w;
#pragma unroll
        for (int nt = 0; nt < 2; ++nt)
#pragma unroll
            for (int j = 0; j < 4; ++j) { aL1[nt][j] = 0.0f; aL2[nt][j] = 0.0f; }
        if (t + 1 < T) {
            const float4* nx = (const float4*)(xp + (size_t)(t + 1) * 2048 + ns * 256 + lane * 8);
            xv0 = nx[0]; xv1 = nx[1];
        }
#pragma unroll
        for (int kc = 0; kc < 8; ++kc) {
            uint4 ah = *(const uint4*)&AsH[p * 1024 + kc * 128 + lane * 4];
            uint4 al = *(const uint4*)&AsL[p * 1024 + kc * 128 + lane * 4];
#pragma unroll
            for (int nt = 0; nt < 2; ++nt) {
                mma16(aH[nt],  ah, Bhi[kc][nt]);
                mma16(aL1[nt], al, Bhi[kc][nt]);
                mma16(aL2[nt], ah, Blo[kc][nt]);
            }
        }

        float y[2][4];
#pragma unroll
        for (int nt = 0; nt < 2; ++nt)
#pragma unroll
            for (int j = 0; j < 4; ++j)
                y[nt][j] = fast_tanh(aH[nt][j] + aL1[nt][j] + aL2[nt][j]);

        // pack h (hi/lo f16): exactly the A-fragment words for (r, col) pairs
        uint4 hv, lv;
        {
            __half h0, l0, h1, l1;
            split16(y[0][0], h0, l0); split16(y[0][1], h1, l1);
            hv.x = pack2(h0, h1); lv.x = pack2(l0, l1);
            split16(y[0][2], h0, l0); split16(y[0][3], h1, l1);
            hv.y = pack2(h0, h1); lv.y = pack2(l0, l1);
            split16(y[1][0], h0, l0); split16(y[1][1], h1, l1);
            hv.z = pack2(h0, h1); lv.z = pack2(l0, l1);
            split16(y[1][2], h0, l0); split16(y[1][3], h1, l1);
            hv.w = pack2(h0, h1); lv.w = pack2(l0, l1);
        }
        const int wbase = (1 - p) * 1024 + ns * 128 + lane * 4;
        *(uint4*)&AsH[wbase] = hv;
        *(uint4*)&AsL[wbase] = lv;

        if (!last) {
            uint32_t* ob = outp + actbase + (size_t)t * 2048 + ns * 128 + lane * 4;
            *(uint4*)ob          = hv;
            *(uint4*)(ob + 1024) = lv;
        } else if (t == T - 1) {
#pragma unroll
            for (int nt = 0; nt < 2; ++nt) {
                int c0 = ns * 16 + nt * 8 + 2 * tig;
                *(float2*)&hlast[(size_t)(b0 + grp)     * H + c0] =
                    make_float2(y[nt][0], y[nt][1]);
                *(float2*)&hlast[(size_t)(b0 + grp + 8) * H + c0] =
                    make_float2(y[nt][2], y[nt][3]);
            }
        }

        __syncthreads();
        p ^= 1;
    }
}

// ---------------------------------------------------------------------------
// Final FC on last timestep
// ---------------------------------------------------------------------------
__global__ void fc_kernel(const float* __restrict__ hlast, const float* __restrict__ fcW,
                          const float* __restrict__ fcb, float* __restrict__ out)
{
    int i = blockIdx.x * blockDim.x + threadIdx.x;
    if (i >= B * NC) return;
    int b = i / NC, c = i - b * NC;
    const float* h = hlast + (size_t)b * H;
    const float* wgt = fcW + c * H;
    float s = fcb[c];
#pragma unroll 8
    for (int k = 0; k < H; ++k) s += h[k] * wgt[k];
    out[i] = s;
}

extern "C" void kernel_launch(void* const* d_in, const int* in_sizes, int n_in,
                              void* d_out, int out_size)
{
    const float* x    = (const float*)d_in[0];
    const float* Wih0 = (const float*)d_in[1];
    const float* Wih  = (const float*)d_in[2];
    const float* Whh  = (const float*)d_in[3];
    const float* bih  = (const float*)d_in[4];
    const float* bhh  = (const float*)d_in[5];
    const float* fcW  = (const float*)d_in[6];
    const float* fcb  = (const float*)d_in[7];
    float* out = (float*)d_out;

    uint32_t *actA, *actB;
    float *xps, *hlast;
    cudaGetSymbolAddress((void**)&actA,  g_actA);
    cudaGetSymbolAddress((void**)&actB,  g_actB);
    cudaGetSymbolAddress((void**)&xps,   g_xp);
    cudaGetSymbolAddress((void**)&hlast, g_hlast);

    // Layer 0: fp32 input, packed output
    rnn_layer<F0><<<CTAS, NT>>>(x, nullptr, Wih0, Whh, bih, bhh,
                                actA, hlast, xps, 0);

    const uint32_t* cur = actA;
    uint32_t* nxt = actB;
    for (int l = 1; l < NL; ++l) {
        int last = (l == NL - 1) ? 1 : 0;
        rnn_layer<H><<<CTAS, NT>>>(nullptr, cur,
                                   Wih + (size_t)(l - 1) * H * H,
                                   Whh + (size_t)l * H * H,
                                   bih + (size_t)l * H,
                                   bhh + (size_t)l * H,
                                   nxt, hlast, xps, last);
        const uint32_t* tmp = nxt;
        nxt = (uint32_t*)cur;
        cur = tmp;
    }

    fc_kernel<<<(B * NC + 255) / 256, 256>>>(hlast, fcW, fcb, out);
}